// round 4
// baseline (speedup 1.0000x reference)
#include <cuda_runtime.h>
#include <math.h>

#define B_   128
#define T_   2048
#define O_   128
#define E_   512
#define L_   34
#define KTOT 768          // 512 (y1) + 128 (c1) + 128 (sh1)
#define NG   512          // 4*O gates
#define KSPL 16           // split-K blocks
#define KPER (KTOT / KSPL)  // 48 = 3 tiles of 16
#define BN_G 64           // gemm N tile
#define SCH  8            // attention chunk-blocks per batch row
#define TCH  (T_ / SCH)   // 256

// d_out layout: out[128*34] | c[128*128] | sh[128*128] | sc[128*128]
#define OUT_OFF_C   (B_ * L_)
#define OUT_OFF_SH  (OUT_OFF_C + B_ * O_)
#define OUT_OFF_SC  (OUT_OFF_SH + B_ * O_)

// ---------------- device scratch ----------------
__device__ __align__(16) float g_part[KSPL][B_ * NG];
__device__ int   g_len[B_];
__device__ float g_pm[B_ * SCH];
__device__ float g_pr[B_ * SCH];
__device__ __align__(16) float g_pacc[B_ * SCH * O_];
__device__ int   g_cnt[B_];   // zero-init; self-resetting ticket

#define N_GEMM_BLK (NG / BN_G * KSPL)   // 8 * 16 = 128

// ---------------- launch 1: GEMM (split-K, 8x4 reg tile) + len, dispatched on blockIdx ----------------
__global__ void gemm_len_kernel(const float* __restrict__ y1, const float* __restrict__ c1,
                                const float* __restrict__ sh1,
                                const float* __restrict__ Wih, const float* __restrict__ Whh,
                                const float* __restrict__ mask) {
    int bid = blockIdx.x;
    int tid = threadIdx.x;

    if (bid >= N_GEMM_BLK) {
        // ---- length path: one block per batch row ----
        __shared__ float s[8];
        int b = bid - N_GEMM_BLK;
        int lane = tid & 31, warp = tid >> 5;
        const float4* m4 = (const float4*)(mask + (size_t)b * T_);
        float acc = 0.f;
        for (int i = tid; i < T_ / 4; i += 256) {
            float4 v = m4[i];
            acc += v.x + v.y + v.z + v.w;
        }
#pragma unroll
        for (int off = 16; off; off >>= 1) acc += __shfl_xor_sync(0xffffffffu, acc, off);
        if (lane == 0) s[warp] = acc;
        __syncthreads();
        if (tid == 0) {
            float t = 0.f;
            for (int w = 0; w < 8; w++) t += s[w];
            g_len[b] = (int)(t + 0.5f);
        }
        return;
    }

    // ---- gemm path: BM=128 (all batch rows), BN=64, BK=16, KPER=48 per block ----
    __shared__ float As[16][132];   // [k][m], 132*4B row stride (16B aligned)
    __shared__ float Bs[16][68];    // [k][n]
    int ks = bid >> 3;              // 0..15
    int n0 = (bid & 7) * BN_G;
    int tm = tid >> 4;              // 0..15 -> rows tm*8 .. tm*8+7
    int tn = tid & 15;              // 0..15 -> cols tn*4 .. tn*4+3

    float acc[8][4];
#pragma unroll
    for (int i = 0; i < 8; i++)
#pragma unroll
        for (int j = 0; j < 4; j++) acc[i][j] = 0.f;

    int alr = tid >> 1;             // 0..127 (A row)
    int alc = (tid & 1) * 8;        // 0 or 8 (A k-offset, 2 float4s)
    int blr = tid >> 2;             // 0..63 (B row)
    int blc = (tid & 3) * 4;        // 0,4,8,12

    for (int kt = 0; kt < KPER; kt += 16) {
        int k0 = ks * KPER + kt;    // 16-aligned; tiles never straddle 512/640
        // A tile load (segment select per tile)
        const float* xs;
        if (k0 < E_)           xs = y1  + (size_t)alr * E_ + k0 + alc;
        else if (k0 < E_ + O_) xs = c1  + (size_t)alr * O_ + (k0 - E_) + alc;
        else                   xs = sh1 + (size_t)alr * O_ + (k0 - E_ - O_) + alc;
        float4 a0 = *(const float4*)xs;
        float4 a1 = *(const float4*)(xs + 4);
        As[alc + 0][alr] = a0.x; As[alc + 1][alr] = a0.y;
        As[alc + 2][alr] = a0.z; As[alc + 3][alr] = a0.w;
        As[alc + 4][alr] = a1.x; As[alc + 5][alr] = a1.y;
        As[alc + 6][alr] = a1.z; As[alc + 7][alr] = a1.w;
        // B tile load
        const float* ws;
        if (k0 < E_ + O_) ws = Wih + (size_t)(n0 + blr) * (E_ + O_) + k0 + blc;
        else              ws = Whh + (size_t)(n0 + blr) * O_ + (k0 - E_ - O_) + blc;
        float4 wv = *(const float4*)ws;
        Bs[blc + 0][blr] = wv.x; Bs[blc + 1][blr] = wv.y;
        Bs[blc + 2][blr] = wv.z; Bs[blc + 3][blr] = wv.w;
        __syncthreads();
#pragma unroll
        for (int k = 0; k < 16; k++) {
            float4 bv = *(const float4*)&Bs[k][tn * 4];
            float4 av0 = *(const float4*)&As[k][tm * 8];
            float4 av1 = *(const float4*)&As[k][tm * 8 + 4];
            float am[8] = {av0.x, av0.y, av0.z, av0.w, av1.x, av1.y, av1.z, av1.w};
#pragma unroll
            for (int i = 0; i < 8; i++) {
                acc[i][0] += am[i] * bv.x;
                acc[i][1] += am[i] * bv.y;
                acc[i][2] += am[i] * bv.z;
                acc[i][3] += am[i] * bv.w;
            }
        }
        __syncthreads();
    }
    float* P = g_part[ks];
#pragma unroll
    for (int i = 0; i < 8; i++) {
        int m = tm * 8 + i;
        *(float4*)&P[m * NG + n0 + tn * 4] = make_float4(acc[i][0], acc[i][1], acc[i][2], acc[i][3]);
    }
}

// ---------------- launch 2: reduce split-K + LSTM activations ----------------
__device__ __forceinline__ float sigf(float x) { return 1.f / (1.f + __expf(-x)); }

__global__ void act_kernel(const float* __restrict__ sc1,
                           const float* __restrict__ bih, const float* __restrict__ bhh,
                           float* __restrict__ dout) {
    int i = blockIdx.x * blockDim.x + threadIdx.x;
    if (i >= B_ * O_) return;
    int b = i >> 7, o = i & 127;
    float g4[4];
#pragma unroll
    for (int gi = 0; gi < 4; gi++) {
        int n = gi * O_ + o;
        float v = bih[n] + bhh[n];
#pragma unroll
        for (int ks = 0; ks < KSPL; ks++) v += g_part[ks][b * NG + n];
        g4[gi] = v;
    }
    float sc = sigf(g4[1]) * sc1[i] + sigf(g4[0]) * tanhf(g4[2]);
    float sh = sigf(g4[3]) * tanhf(sc);
    dout[OUT_OFF_SC + i] = sc;
    dout[OUT_OFF_SH + i] = sh;
}

// ---------------- attention group body ----------------
template <bool FULL>
__device__ __forceinline__ void attn_group(const float4* __restrict__ hk4,
                                           const float4* __restrict__ hv4,
                                           int t, int len, float4 q, int lane,
                                           float& m, float& r, float4& acc) {
    int b0 = t * (O_ / 4);
    float4 k0 = hk4[b0 + lane];
    float4 k1 = hk4[b0 + 32 + lane];
    float4 k2 = hk4[b0 + 64 + lane];
    float4 k3 = hk4[b0 + 96 + lane];
    float4 v0 = hv4[b0 + lane];
    float4 v1 = hv4[b0 + 32 + lane];
    float4 v2 = hv4[b0 + 64 + lane];
    float4 v3 = hv4[b0 + 96 + lane];
    float d0 = k0.x * q.x + k0.y * q.y + k0.z * q.z + k0.w * q.w;
    float d1 = k1.x * q.x + k1.y * q.y + k1.z * q.z + k1.w * q.w;
    float d2 = k2.x * q.x + k2.y * q.y + k2.z * q.z + k2.w * q.w;
    float d3 = k3.x * q.x + k3.y * q.y + k3.z * q.z + k3.w * q.w;
#pragma unroll
    for (int off = 16; off; off >>= 1) {
        d0 += __shfl_xor_sync(0xffffffffu, d0, off);
        d1 += __shfl_xor_sync(0xffffffffu, d1, off);
        d2 += __shfl_xor_sync(0xffffffffu, d2, off);
        d3 += __shfl_xor_sync(0xffffffffu, d3, off);
    }
    if (!FULL) {
        // prefix mask: t valid (caller guarantees), t+j valid iff t+j < len
        d1 = (t + 1 < len) ? d1 : -INFINITY;
        d2 = (t + 2 < len) ? d2 : -INFINITY;
        d3 = (t + 3 < len) ? d3 : -INFINITY;
    }
    float g = fmaxf(fmaxf(d0, d1), fmaxf(d2, d3));
    float nm = fmaxf(m, g);
    float e0 = __expf(d0 - nm);
    float e1 = __expf(d1 - nm);
    float e2 = __expf(d2 - nm);
    float e3 = __expf(d3 - nm);
    float scale = __expf(m - nm);
    acc.x = acc.x * scale + e0 * v0.x + e1 * v1.x + e2 * v2.x + e3 * v3.x;
    acc.y = acc.y * scale + e0 * v0.y + e1 * v1.y + e2 * v2.y + e3 * v3.y;
    acc.z = acc.z * scale + e0 * v0.z + e1 * v1.z + e2 * v2.z + e3 * v3.z;
    acc.w = acc.w * scale + e0 * v0.w + e1 * v1.w + e2 * v2.w + e3 * v3.w;
    r = r * scale + (e0 + e1 + e2 + e3);
    m = nm;
}

// ---------------- launch 3: attention partials + fused combine/MLP in last block ----------------
// grid (SCH, B_), 256 threads. Warp w covers t in [chunk*256 + w*32, +32) ∩ [0, len).
__global__ void attn_kernel(const float* __restrict__ hk, const float* __restrict__ hv,
                            float* __restrict__ dout,
                            const float* __restrict__ W1, const float* __restrict__ b1,
                            const float* __restrict__ W2, const float* __restrict__ b2,
                            const float* __restrict__ W3, const float* __restrict__ b3) {
    __shared__ float s_m[8], s_r[8];
    __shared__ float s_acc[8][O_];
    __shared__ int s_last;
    int b = blockIdx.y;
    int chunk = blockIdx.x;
    int tid = threadIdx.x;
    int warp = tid >> 5, lane = tid & 31;

    float4 q = ((const float4*)(dout + OUT_OFF_SC + b * O_))[lane];
    const float4* hk4 = (const float4*)(hk) + (size_t)b * T_ * (O_ / 4);
    const float4* hv4 = (const float4*)(hv) + (size_t)b * T_ * (O_ / 4);

    int len = g_len[b];
    int t0 = chunk * TCH + warp * 32;
    int v = len - t0;                          // valid t count in this warp's chunk

    float m = -INFINITY, r = 0.f;
    float4 acc = make_float4(0.f, 0.f, 0.f, 0.f);

    if (v >= 32) {
#pragma unroll
        for (int i = 0; i < 32; i += 4)
            attn_group<true>(hk4, hv4, t0 + i, len, q, lane, m, r, acc);
    } else if (v > 0) {
        for (int i = 0; i < v; i += 4)
            attn_group<false>(hk4, hv4, t0 + i, len, q, lane, m, r, acc);
    }

    s_acc[warp][4 * lane + 0] = acc.x;
    s_acc[warp][4 * lane + 1] = acc.y;
    s_acc[warp][4 * lane + 2] = acc.z;
    s_acc[warp][4 * lane + 3] = acc.w;
    if (lane == 0) { s_m[warp] = m; s_r[warp] = r; }
    __syncthreads();

    // block combine -> partials
    if (tid < O_) {
        float M = -INFINITY;
#pragma unroll
        for (int w = 0; w < 8; w++) if (s_r[w] > 0.f) M = fmaxf(M, s_m[w]);
        float R = 0.f, A = 0.f;
#pragma unroll
        for (int w = 0; w < 8; w++) {
            if (s_r[w] > 0.f) {
                float f = __expf(s_m[w] - M);
                R += s_r[w] * f;
                A += s_acc[w][tid] * f;
            }
        }
        int p = b * SCH + chunk;
        g_pacc[p * O_ + tid] = A;
        if (tid == 0) { g_pm[p] = M; g_pr[p] = R; }
    }
    __syncthreads();

    // last-block ticket: the 8th block for this batch row does combine + MLP
    if (tid == 0) {
        __threadfence();
        int old = atomicAdd(&g_cnt[b], 1);
        if (old == SCH - 1) { g_cnt[b] = 0; s_last = 1; } else { s_last = 0; }
    }
    __syncthreads();
    if (!s_last) return;
    __threadfence();   // make other blocks' partials visible

    // ---- fused combine -> c, then MLP + softmax (reuse shared) ----
    __shared__ float shs[O_], cs[O_], h[L_], z[L_];
    __shared__ float sM, sZ;
    if (tid == 0) {
        float M = -INFINITY;
        for (int s = 0; s < SCH; s++) if (g_pr[b * SCH + s] > 0.f) M = fmaxf(M, g_pm[b * SCH + s]);
        float Z = 0.f;
        for (int s = 0; s < SCH; s++)
            if (g_pr[b * SCH + s] > 0.f) Z += g_pr[b * SCH + s] * __expf(g_pm[b * SCH + s] - M);
        sM = M; sZ = Z;
    }
    if (tid < O_) shs[tid] = dout[OUT_OFF_SH + b * O_ + tid];
    __syncthreads();
    if (tid < O_) {
        float A = 0.f;
#pragma unroll
        for (int s = 0; s < SCH; s++) {
            if (g_pr[b * SCH + s] > 0.f)
                A += g_pacc[(b * SCH + s) * O_ + tid] * __expf(g_pm[b * SCH + s] - sM);
        }
        float cval = A / sZ;
        cs[tid] = cval;
        dout[OUT_OFF_C + b * O_ + tid] = cval;
    }
    __syncthreads();
    if (tid < L_) {
        float a = b1[tid] + b2[tid];
        const float* w1 = &W1[tid * O_];
        const float* w2 = &W2[tid * O_];
#pragma unroll 4
        for (int k = 0; k < O_; k++) a += shs[k] * w1[k] + cs[k] * w2[k];
        h[tid] = fmaxf(a, 0.f);
    }
    __syncthreads();
    if (tid < L_) {
        float a = b3[tid];
        const float* w3 = &W3[tid * L_];
#pragma unroll
        for (int j = 0; j < L_; j++) a += h[j] * w3[j];
        z[tid] = a;
    }
    __syncthreads();
    if (tid == 0) {
        float M = -INFINITY;
        for (int j = 0; j < L_; j++) M = fmaxf(M, z[j]);
        float S = 0.f;
        for (int j = 0; j < L_; j++) { float e = __expf(z[j] - M); z[j] = e; S += e; }
        float inv = 1.f / S;
        for (int j = 0; j < L_; j++) dout[b * L_ + j] = z[j] * inv;
    }
}

// ---------------- launcher ----------------
extern "C" void kernel_launch(void* const* d_in, const int* in_sizes, int n_in,
                              void* d_out, int out_size) {
    const float* P[17];
    if (n_in >= 17 && in_sizes[0] == B_ * T_ * O_) {
        for (int i = 0; i < 17; i++) P[i] = (const float*)d_in[i];
    } else {
        // alphabetical key order fallback
        P[0]  = (const float*)d_in[11];  // hk
        P[1]  = (const float*)d_in[12];  // hv
        P[2]  = (const float*)d_in[16];  // y_1
        P[3]  = (const float*)d_in[10];  // c_1
        P[4]  = (const float*)d_in[15];  // sh_1
        P[5]  = (const float*)d_in[14];  // sc_1
        P[6]  = (const float*)d_in[13];  // mask
        P[7]  = (const float*)d_in[4];   // W_ih
        P[8]  = (const float*)d_in[9];   // b_ih
        P[9]  = (const float*)d_in[3];   // W_hh
        P[10] = (const float*)d_in[8];   // b_hh
        P[11] = (const float*)d_in[0];   // W1
        P[12] = (const float*)d_in[5];   // b1
        P[13] = (const float*)d_in[1];   // W2
        P[14] = (const float*)d_in[6];   // b2
        P[15] = (const float*)d_in[2];   // W3
        P[16] = (const float*)d_in[7];   // b3
    }
    const float *hk = P[0], *hv = P[1], *y1 = P[2], *c1 = P[3], *sh1 = P[4], *sc1 = P[5];
    const float *mask = P[6], *Wih = P[7], *bih = P[8], *Whh = P[9], *bhh = P[10];
    const float *W1 = P[11], *b1 = P[12], *W2 = P[13], *b2 = P[14], *W3 = P[15], *b3 = P[16];
    float* dout = (float*)d_out;

    gemm_len_kernel<<<N_GEMM_BLK + B_, 256>>>(y1, c1, sh1, Wih, Whh, mask);
    act_kernel<<<(B_ * O_ + 255) / 256, 256>>>(sc1, bih, bhh, dout);
    attn_kernel<<<dim3(SCH, B_), 256>>>(hk, hv, dout, W1, b1, W2, b2, W3, b3);
}